// round 1
// baseline (speedup 1.0000x reference)
#include <cuda_runtime.h>
#include <cuda_bf16.h>

// IF spiking neuron forward (non-align, T>0):
//   x: [T*B, 1024, 3072] fp32, thresh2: [1024,3072], dtmem: [1024,3072]
//   mem = dtmem*thre; for t: mem += x_t; spike = (mem-thre>=0)?thre:0; mem -= spike
// Pure streaming, HBM-bound. One thread owns one float4 "column" across T steps.

#define T_STEPS 4
#define B_BATCH 8
#define FEAT_N  (1024LL * 3072LL)          // 3,145,728 feature elements
#define N4      ((unsigned)(FEAT_N / 4))   // 786,432 float4 per feature map
#define TOTAL4  ((unsigned)(B_BATCH * (FEAT_N / 4)))  // 6,291,456 float4 per timestep

__global__ __launch_bounds__(256) void if_fwd_kernel(
    const float4* __restrict__ x,
    const float4* __restrict__ thresh,
    const float4* __restrict__ dtm,
    float4* __restrict__ out)
{
    unsigned j = blockIdx.x * blockDim.x + threadIdx.x;
    if (j >= TOTAL4) return;

    unsigned f = j % N4;                 // feature float4 index (const-divisor, fast)

    const float4 th = __ldg(&thresh[f]);
    const float4 dm = __ldg(&dtm[f]);

    float mx = dm.x * th.x;
    float my = dm.y * th.y;
    float mz = dm.z * th.z;
    float mw = dm.w * th.w;

#pragma unroll
    for (int t = 0; t < T_STEPS; ++t) {
        const float4 xv = __ldg(&x[(unsigned)t * TOTAL4 + j]);

        mx += xv.x; my += xv.y; mz += xv.z; mw += xv.w;

        float4 sp;
        sp.x = (mx - th.x >= 0.0f) ? th.x : 0.0f;
        sp.y = (my - th.y >= 0.0f) ? th.y : 0.0f;
        sp.z = (mz - th.z >= 0.0f) ? th.z : 0.0f;
        sp.w = (mw - th.w >= 0.0f) ? th.w : 0.0f;

        mx -= sp.x; my -= sp.y; mz -= sp.z; mw -= sp.w;

        out[(unsigned)t * TOTAL4 + j] = sp;
    }
}

extern "C" void kernel_launch(void* const* d_in, const int* in_sizes, int n_in,
                              void* d_out, int out_size)
{
    const float4* x      = (const float4*)d_in[0];
    const float4* thresh = (const float4*)d_in[1];
    const float4* dtm    = (const float4*)d_in[2];
    float4* out          = (float4*)d_out;

    const int threads = 256;
    const int blocks  = (TOTAL4 + threads - 1) / threads;
    if_fwd_kernel<<<blocks, threads>>>(x, thresh, dtm, out);
}

// round 3
// speedup vs baseline: 1.1397x; 1.1397x over previous
#include <cuda_runtime.h>
#include <cuda_bf16.h>

// IF spiking neuron forward (non-align, T>0):
//   x: [T, B, 1024, 3072] fp32 (flattened T*B), thresh2/dtmem: [1024,3072]
//   mem0 = dtmem*thre (same for every batch); per t: mem += x_t; spike = (mem>=thre)?thre:0; mem -= spike
//
// One thread owns one float4 feature column for ALL 8 batches x 4 timesteps.
// -> thresh/dtm read exactly once per f (kills the ~124MB of L2-evicted param
//    re-fetch seen in R1), 8 independent load/store streams per timestep for
//    MLP, streaming (evict-first) hints on the read-once/write-once data.

#define T_STEPS 4
#define B_BATCH 8
#define FEAT_N  (1024u * 3072u)       // 3,145,728 feature elements
#define N4      (FEAT_N / 4u)         // 786,432 float4 per feature map

__global__ __launch_bounds__(256) void if_fwd_kernel(
    const float4* __restrict__ x,
    const float4* __restrict__ thresh,
    const float4* __restrict__ dtm,
    float4* __restrict__ out)
{
    unsigned f = blockIdx.x * blockDim.x + threadIdx.x;
    if (f >= N4) return;

    const float4 th = __ldg(&thresh[f]);
    const float4 dm = __ldg(&dtm[f]);

    // mem[b] — same init for every batch (mem0 = dtmem * thre, broadcast over B)
    float4 mem[B_BATCH];
#pragma unroll
    for (int b = 0; b < B_BATCH; ++b) {
        mem[b].x = dm.x * th.x;
        mem[b].y = dm.y * th.y;
        mem[b].z = dm.z * th.z;
        mem[b].w = dm.w * th.w;
    }

#pragma unroll
    for (int t = 0; t < T_STEPS; ++t) {
        const float4* __restrict__ xt = x   + (size_t)t * B_BATCH * N4 + f;
        float4* __restrict__       ot = out + (size_t)t * B_BATCH * N4 + f;

        // 8 independent streams this timestep; front-batch the loads for MLP.
        float4 xv[B_BATCH];
#pragma unroll
        for (int b = 0; b < B_BATCH; ++b) {
            xv[b] = __ldcs(xt + (size_t)b * N4);
        }
#pragma unroll
        for (int b = 0; b < B_BATCH; ++b) {
            mem[b].x += xv[b].x;
            mem[b].y += xv[b].y;
            mem[b].z += xv[b].z;
            mem[b].w += xv[b].w;

            float4 sp;
            sp.x = (mem[b].x - th.x >= 0.0f) ? th.x : 0.0f;
            sp.y = (mem[b].y - th.y >= 0.0f) ? th.y : 0.0f;
            sp.z = (mem[b].z - th.z >= 0.0f) ? th.z : 0.0f;
            sp.w = (mem[b].w - th.w >= 0.0f) ? th.w : 0.0f;

            mem[b].x -= sp.x;
            mem[b].y -= sp.y;
            mem[b].z -= sp.z;
            mem[b].w -= sp.w;

            __stcs(ot + (size_t)b * N4, sp);
        }
    }
}

extern "C" void kernel_launch(void* const* d_in, const int* in_sizes, int n_in,
                              void* d_out, int out_size)
{
    const float4* x      = (const float4*)d_in[0];
    const float4* thresh = (const float4*)d_in[1];
    const float4* dtm    = (const float4*)d_in[2];
    float4* out          = (float4*)d_out;

    const int threads = 256;
    const int blocks  = (N4 + threads - 1) / threads;   // 3072 blocks
    if_fwd_kernel<<<blocks, threads>>>(x, thresh, dtm, out);
}

// round 4
// speedup vs baseline: 1.1609x; 1.0186x over previous
#include <cuda_runtime.h>
#include <cuda_bf16.h>

// IF spiking neuron forward (non-align, T>0):
//   x: [T, B, 1024, 3072] fp32 (flattened T*B), thresh2/dtmem: [1024,3072]
//   mem0 = dtmem*thre (same for every batch); per t: mem += x_t; spike = (mem>=thre)?thre:0; mem -= spike
//
// R4: one thread owns one float4 feature column for 4 batches x 4 timesteps
// (was 8 batches -> regs=72, occ=34% -> DRAM pipe underfed at 76.9%).
// Batch-half lives in the LOW bit of blockIdx.x so the two blocks sharing a
// 256-f param range are wave-adjacent: second param read hits L2, keeping the
// DRAM traffic at the ~830MB floor while occupancy ~doubles.

#define T_STEPS  4
#define B_BATCH  8
#define B_PER_TH 4
#define FEAT_N   (1024u * 3072u)      // 3,145,728 feature elements
#define N4       (FEAT_N / 4u)        // 786,432 float4 per feature map

__global__ __launch_bounds__(256) void if_fwd_kernel(
    const float4* __restrict__ x,
    const float4* __restrict__ thresh,
    const float4* __restrict__ dtm,
    float4* __restrict__ out)
{
    const unsigned bid   = blockIdx.x;
    const unsigned f     = (bid >> 1) * 256u + threadIdx.x;   // feature float4 index
    const unsigned bbase = (bid & 1u) * B_PER_TH;             // batch half: 0..3 or 4..7
    if (f >= N4) return;

    const float4 th = __ldg(&thresh[f]);
    const float4 dm = __ldg(&dtm[f]);

    // mem[b] — same init for every batch (mem0 = dtmem * thre, broadcast over B)
    float4 mem[B_PER_TH];
#pragma unroll
    for (int b = 0; b < B_PER_TH; ++b) {
        mem[b].x = dm.x * th.x;
        mem[b].y = dm.y * th.y;
        mem[b].z = dm.z * th.z;
        mem[b].w = dm.w * th.w;
    }

#pragma unroll
    for (int t = 0; t < T_STEPS; ++t) {
        const float4* __restrict__ xt = x   + ((size_t)t * B_BATCH + bbase) * N4 + f;
        float4* __restrict__       ot = out + ((size_t)t * B_BATCH + bbase) * N4 + f;

        // 4 independent streams this timestep; front-batch the loads for MLP.
        float4 xv[B_PER_TH];
#pragma unroll
        for (int b = 0; b < B_PER_TH; ++b) {
            xv[b] = __ldcs(xt + (size_t)b * N4);
        }
#pragma unroll
        for (int b = 0; b < B_PER_TH; ++b) {
            mem[b].x += xv[b].x;
            mem[b].y += xv[b].y;
            mem[b].z += xv[b].z;
            mem[b].w += xv[b].w;

            float4 sp;
            sp.x = (mem[b].x - th.x >= 0.0f) ? th.x : 0.0f;
            sp.y = (mem[b].y - th.y >= 0.0f) ? th.y : 0.0f;
            sp.z = (mem[b].z - th.z >= 0.0f) ? th.z : 0.0f;
            sp.w = (mem[b].w - th.w >= 0.0f) ? th.w : 0.0f;

            mem[b].x -= sp.x;
            mem[b].y -= sp.y;
            mem[b].z -= sp.z;
            mem[b].w -= sp.w;

            __stcs(ot + (size_t)b * N4, sp);
        }
    }
}

extern "C" void kernel_launch(void* const* d_in, const int* in_sizes, int n_in,
                              void* d_out, int out_size)
{
    const float4* x      = (const float4*)d_in[0];
    const float4* thresh = (const float4*)d_in[1];
    const float4* dtm    = (const float4*)d_in[2];
    float4* out          = (float4*)d_out;

    const int threads = 256;
    const int blocks  = (N4 / threads) * 2;   // 6144 blocks (N4 divisible by 256)
    if_fwd_kernel<<<blocks, threads>>>(x, thresh, dtm, out);
}